// round 6
// baseline (speedup 1.0000x reference)
#include <cuda_runtime.h>
#include <cstdint>
#include <cstddef>

// Problem dims
static constexpr int Bc = 32;
static constexpr int Tc = 2048;
static constexpr int Dc = 256;
static constexpr int Hc = 512;
static constexpr int Oc = 256;
static constexpr int BT = Bc * Tc;          // 65536

// Scratch (static device arrays — allocation-free per harness rules)
__device__ float g_xw[(size_t)BT * Hc];     // 128 MB: x@W_ih^T + bias
__device__ float g_z [(size_t)BT * Hc];     // 128 MB: fallback z storage

// ---------------------------------------------------------------------------
// Packed f32x2 helpers (sm_100+ dual-FP32 pipe)
// ---------------------------------------------------------------------------
__device__ __forceinline__ void fma2(unsigned long long& d,
                                     unsigned long long a,
                                     unsigned long long b) {
    asm("fma.rn.f32x2 %0, %1, %2, %0;" : "+l"(d) : "l"(a), "l"(b));
}
__device__ __forceinline__ unsigned long long pack2(float lo, float hi) {
    unsigned long long p;
    asm("mov.b64 %0, {%1, %2};" : "=l"(p) : "f"(lo), "f"(hi));
    return p;
}
__device__ __forceinline__ float unpack_sum(unsigned long long a) {
    float lo, hi;
    asm("mov.b64 {%0, %1}, %2;" : "=f"(lo), "=f"(hi) : "l"(a));
    return lo + hi;
}
__device__ __forceinline__ void unpack2(unsigned long long a, float& lo, float& hi) {
    asm("mov.b64 {%0, %1}, %2;" : "=f"(lo), "=f"(hi) : "l"(a));
}

// mbarrier wait on a LOCAL barrier with cluster-scope acquire (pairs with the
// peers' release.cluster arrives).
#define MBAR_WAIT_CLUSTER(mbar, parity) do {                                   \
    asm volatile(                                                              \
        "{\n\t"                                                                \
        ".reg .pred P1;\n\t"                                                   \
        "WL_%=:\n\t"                                                           \
        "mbarrier.try_wait.parity.acquire.cluster.shared::cta.b64 P1, [%0], %1, 0x989680;\n\t" \
        "@P1 bra.uni WD_%=;\n\t"                                               \
        "bra.uni WL_%=;\n\t"                                                   \
        "WD_%=:\n\t"                                                           \
        "}"                                                                    \
        :: "r"(mbar), "r"(parity) : "memory");                                 \
} while (0)

// Remote arrive with EXPLICIT cluster-scope release (PTX default is
// .release.cta, which was the R5 correctness bug: the cross-CTA
// synchronizes-with edge was never established at cluster scope).
#define MBAR_ARRIVE_REL_CLUSTER(addr)                                          \
    asm volatile("mbarrier.arrive.release.cluster.shared::cluster.b64 _, [%0];"\
                 :: "r"(addr) : "memory")

// ---------------------------------------------------------------------------
// Kernel 1/3: C[M,N] = A[M,K] @ B[N,K]^T + bias1[N] (+ bias2[N])
// 128x128x16 fp32 tile, 256 threads, 8x8 microtile, double-buffered,
// inner product on the packed f32x2 pipe (FFMA2: 2 MACs/instr).
// ---------------------------------------------------------------------------
__global__ void __launch_bounds__(256, 2)
gemm_tn_kernel(const float* __restrict__ A, const float* __restrict__ Bm,
               const float* __restrict__ bias1, const float* __restrict__ bias2,
               float* __restrict__ C, int M, int N, int K)
{
    __shared__ __align__(16) float As[2][16][128];
    __shared__ __align__(16) float Bs[2][16][128];

    const int tid = threadIdx.x;
    const int bm = blockIdx.x * 128;
    const int bn = blockIdx.y * 128;
    const int lr = tid >> 2;            // 0..63  (row within tile, +64 on 2nd pass)
    const int lk = (tid & 3) << 2;      // 0,4,8,12 (k offset, float4)
    const int tm = (tid >> 4) << 3;     // 0..120 step 8
    const int tn = (tid & 15) << 3;     // 0..120 step 8

    // acc2[i][jp] = packed pair of output columns {tn+2jp, tn+2jp+1}
    unsigned long long acc2[8][4];
#pragma unroll
    for (int i = 0; i < 8; i++)
#pragma unroll
        for (int j = 0; j < 4; j++) acc2[i][j] = 0ull;

    auto load_tile = [&](int buf, int kt) {
#pragma unroll
        for (int p = 0; p < 2; p++) {
            const float4 av = *reinterpret_cast<const float4*>(
                A + (size_t)(bm + lr + p * 64) * K + kt + lk);
            As[buf][lk + 0][lr + p * 64] = av.x;
            As[buf][lk + 1][lr + p * 64] = av.y;
            As[buf][lk + 2][lr + p * 64] = av.z;
            As[buf][lk + 3][lr + p * 64] = av.w;
            const float4 bv = *reinterpret_cast<const float4*>(
                Bm + (size_t)(bn + lr + p * 64) * K + kt + lk);
            Bs[buf][lk + 0][lr + p * 64] = bv.x;
            Bs[buf][lk + 1][lr + p * 64] = bv.y;
            Bs[buf][lk + 2][lr + p * 64] = bv.z;
            Bs[buf][lk + 3][lr + p * 64] = bv.w;
        }
    };

    load_tile(0, 0);
    __syncthreads();

    const int nk = K >> 4;
    for (int kt = 0; kt < nk; kt++) {
        const int cur = kt & 1;
        if (kt + 1 < nk) load_tile(cur ^ 1, (kt + 1) << 4);
#pragma unroll
        for (int kk = 0; kk < 16; kk++) {
            float a[8];
            *reinterpret_cast<float4*>(&a[0]) =
                *reinterpret_cast<const float4*>(&As[cur][kk][tm]);
            *reinterpret_cast<float4*>(&a[4]) =
                *reinterpret_cast<const float4*>(&As[cur][kk][tm + 4]);
            const ulonglong2 b01 =
                *reinterpret_cast<const ulonglong2*>(&Bs[cur][kk][tn]);
            const ulonglong2 b23 =
                *reinterpret_cast<const ulonglong2*>(&Bs[cur][kk][tn + 4]);
#pragma unroll
            for (int i = 0; i < 8; i++) {
                const unsigned long long ap = pack2(a[i], a[i]);
                fma2(acc2[i][0], ap, b01.x);
                fma2(acc2[i][1], ap, b01.y);
                fma2(acc2[i][2], ap, b23.x);
                fma2(acc2[i][3], ap, b23.y);
            }
        }
        __syncthreads();
    }

    // Epilogue: bias + store (float4)
    float bv[8];
#pragma unroll
    for (int j = 0; j < 8; j++) {
        float b = bias1 ? bias1[bn + tn + j] : 0.f;
        if (bias2) b += bias2[bn + tn + j];
        bv[j] = b;
    }
#pragma unroll
    for (int i = 0; i < 8; i++) {
        float c[8];
#pragma unroll
        for (int j = 0; j < 4; j++) unpack2(acc2[i][j], c[2 * j], c[2 * j + 1]);
        float* cp = C + (size_t)(bm + tm + i) * N + bn + tn;
        float4 v0, v1;
        v0.x = c[0] + bv[0]; v0.y = c[1] + bv[1];
        v0.z = c[2] + bv[2]; v0.w = c[3] + bv[3];
        v1.x = c[4] + bv[4]; v1.y = c[5] + bv[5];
        v1.z = c[6] + bv[6]; v1.w = c[7] + bv[7];
        *reinterpret_cast<float4*>(cp)     = v0;
        *reinterpret_cast<float4*>(cp + 4) = v1;
    }
}

// ---------------------------------------------------------------------------
// Kernel 2/3: the sequential recurrence (mbarrier-pipelined version).
// 16 clusters x 8 CTAs; cluster c owns batches {2c, 2c+1} as two independent
// chains processed back-to-back per iteration so one chain's DSMEM push +
// arrive latency drains under the other chain's FMA phase.
//
// Sync protocol (forward-only, no cluster barrier in the loop):
//  - h is TRIPLE-buffered per chain: buf[chain][slot(=s%3)][512].
//  - writers (64/chain) st.shared::cluster their h_new element to all 8 CTAs'
//    buf[chain][(s+1)%3], then a named bar among those 64 writers, then
//    fence.acq_rel.cluster + 8 remote mbarrier.arrive.release.cluster by ONE
//    elected writer. The cta-scope bar.sync orders all writers' remote stores
//    into the elected thread; the cluster-scope fence + release-arrive
//    propagate them (A-cumulativity) to the consumer's acquire.
//  - each barrier expects 8 arrivals/phase (one per source CTA).
//  - consumers try_wait(parity, acquire.cluster) on their local barrier.
//  Triple buffering makes the slot a writer targets provably disjoint from any
//  slot a (<=1-step-behind) peer may still be reading.
// ---------------------------------------------------------------------------
__global__ void __cluster_dims__(8, 1, 1) __launch_bounds__(512, 1)
rnn_scan_kernel(const float* __restrict__ xw, const float* __restrict__ h0,
                const float* __restrict__ W_hh, float* __restrict__ z)
{
    __shared__ __align__(16) float buf[2][3][Hc];      // 12 KB h slots
    __shared__ float red[2][8][64];                    //  4 KB partial sums
    __shared__ __align__(8) unsigned long long mbar[2][3];

    const int tid = threadIdx.x;
    uint32_t rank;
    asm("mov.u32 %0, %%cluster_ctarank;" : "=r"(rank));
    const int cid = blockIdx.x >> 3;
    const int b0  = cid * 2;

    const int jloc  = tid & 63;
    const int kc    = tid >> 6;          // 0..7
    const int jg    = (int)rank * 64 + jloc;
    const int kbase = kc * 64;

    // W_hh[jg][kbase .. kbase+63] -> 32 packed f32x2 registers
    unsigned long long w[32];
    {
        const float4* wp =
            reinterpret_cast<const float4*>(W_hh + (size_t)jg * Hc + kbase);
#pragma unroll
        for (int i = 0; i < 16; i++) {
            float4 v = wp[i];
            w[2 * i]     = pack2(v.x, v.y);
            w[2 * i + 1] = pack2(v.z, v.w);
        }
    }

    // init mbarriers (8 expected arrivals per phase: one per source CTA)
    if (tid == 0) {
#pragma unroll
        for (int c = 0; c < 2; c++)
#pragma unroll
            for (int sl = 0; sl < 3; sl++) {
                uint32_t a = (uint32_t)__cvta_generic_to_shared(&mbar[c][sl]);
                asm volatile("mbarrier.init.shared.b64 [%0], %1;"
                             :: "r"(a), "r"(8) : "memory");
            }
    }
    // h0 into slot 0 of both chains
    for (int idx = tid; idx < 2 * Hc; idx += 512) {
        const int bb = idx >> 9;   // Hc == 512
        const int k  = idx & 511;
        buf[bb][0][k] = h0[(size_t)(b0 + bb) * Hc + k];
    }
    __syncthreads();
    // all CTAs' barriers must be initialized before any remote arrive
    asm volatile("barrier.cluster.arrive.aligned;" ::: "memory");
    asm volatile("barrier.cluster.wait.aligned;" ::: "memory");

    // mapa bases to every peer (mapa is linear in the offset for a fixed rank)
    const uint32_t bufBase  = (uint32_t)__cvta_generic_to_shared(&buf[0][0][0]);
    const uint32_t mbarBase = (uint32_t)__cvta_generic_to_shared(&mbar[0][0]);
    uint32_t peerBuf[8], peerMbar[8];
#pragma unroll
    for (uint32_t rr = 0; rr < 8; rr++) {
        asm("mapa.shared::cluster.u32 %0, %1, %2;"
            : "=r"(peerBuf[rr]) : "r"(bufBase), "r"(rr));
        asm("mapa.shared::cluster.u32 %0, %1, %2;"
            : "=r"(peerMbar[rr]) : "r"(mbarBase), "r"(rr));
    }

    // bootstrap: complete phase 0 of the slot-0 barriers (h0 is preloaded
    // locally, so "slot0 data ready" is signalled by every CTA's thread 0)
    if (tid == 0) {
#pragma unroll
        for (uint32_t rr = 0; rr < 8; rr++) {
            MBAR_ARRIVE_REL_CLUSTER(peerMbar[rr] + 0 * 8);   // chain0 slot0
            MBAR_ARRIVE_REL_CLUSTER(peerMbar[rr] + 3 * 8);   // chain1 slot0
        }
    }

    const size_t bstride = (size_t)Tc * Hc;
    const bool   isW = (tid < 128);
    const int    wb  = (tid >> 6) & 1;   // writer's chain (valid when isW)
    const int    wj  = tid & 63;
    const int    wjg = (int)rank * 64 + wj;
    const float* xwp = xw + (size_t)(b0 + wb) * bstride + wjg;
    float*       zp  = z  + (size_t)(b0 + wb) * bstride + wjg;

    int slot = 0, phase = 0;

    for (int s = 0; s < Tc; s++) {
        float xwv = 0.f;
        if (isW) xwv = __ldg(xwp + (size_t)s * Hc);
        const int  slotN = (slot == 2) ? 0 : slot + 1;
        const bool push  = (s + 1 < Tc);

        // ================= chain A (batch b0) =================
        MBAR_WAIT_CLUSTER(mbarBase + (uint32_t)(slot * 8), phase);
        {
            unsigned long long acc = 0ull;
            const ulonglong2* hp =
                reinterpret_cast<const ulonglong2*>(&buf[0][slot][kbase]);
#pragma unroll
            for (int i = 0; i < 16; i++) {
                const ulonglong2 hv = hp[i];
                fma2(acc, w[2 * i],     hv.x);
                fma2(acc, w[2 * i + 1], hv.y);
            }
            red[0][kc][jloc] = unpack_sum(acc);
        }
        __syncthreads();

        if (tid < 64) {
            float sv = xwv;
#pragma unroll
            for (int q = 0; q < 8; q++) sv += red[0][q][wj];
            zp[(size_t)s * Hc] = sv;
            if (push) {
                const uint32_t off = (uint32_t)((slotN * 512 + wjg) * 4);
#pragma unroll
                for (int rr = 0; rr < 8; rr++)
                    asm volatile("st.shared::cluster.f32 [%0], %1;"
                                 :: "r"(peerBuf[rr] + off), "f"(sv));
            }
            asm volatile("bar.sync 1, 64;" ::: "memory");
            if (tid == 0 && push) {
                asm volatile("fence.acq_rel.cluster;" ::: "memory");
                const uint32_t moff = (uint32_t)(slotN * 8);
#pragma unroll
                for (int rr = 0; rr < 8; rr++)
                    MBAR_ARRIVE_REL_CLUSTER(peerMbar[rr] + moff);
            }
        }

        // ================= chain B (batch b0+1) =================
        MBAR_WAIT_CLUSTER(mbarBase + (uint32_t)((3 + slot) * 8), phase);
        {
            unsigned long long acc = 0ull;
            const ulonglong2* hp =
                reinterpret_cast<const ulonglong2*>(&buf[1][slot][kbase]);
#pragma unroll
            for (int i = 0; i < 16; i++) {
                const ulonglong2 hv = hp[i];
                fma2(acc, w[2 * i],     hv.x);
                fma2(acc, w[2 * i + 1], hv.y);
            }
            red[1][kc][jloc] = unpack_sum(acc);
        }
        __syncthreads();

        if (tid >= 64 && tid < 128) {
            float sv = xwv;
#pragma unroll
            for (int q = 0; q < 8; q++) sv += red[1][q][wj];
            zp[(size_t)s * Hc] = sv;
            if (push) {
                const uint32_t off = (uint32_t)(((3 + slotN) * 512 + wjg) * 4);
#pragma unroll
                for (int rr = 0; rr < 8; rr++)
                    asm volatile("st.shared::cluster.f32 [%0], %1;"
                                 :: "r"(peerBuf[rr] + off), "f"(sv));
            }
            asm volatile("bar.sync 2, 64;" ::: "memory");
            if (tid == 64 && push) {
                asm volatile("fence.acq_rel.cluster;" ::: "memory");
                const uint32_t moff = (uint32_t)((3 + slotN) * 8);
#pragma unroll
                for (int rr = 0; rr < 8; rr++)
                    MBAR_ARRIVE_REL_CLUSTER(peerMbar[rr] + moff);
            }
        }

        slot = slotN;
        if (slot == 0) phase ^= 1;
    }
    // No trailing cluster sync needed: the last remote ops any CTA issues
    // (pushes/arrives for step use T-1, sent at s=T-2) are consumed by every
    // CTA's own wait at s=T-1 before it can exit.
}

// ---------------------------------------------------------------------------
// Kernel 3/3: in-place row softmax over O=256 (one warp per row)
// ---------------------------------------------------------------------------
__global__ void __launch_bounds__(256)
softmax256_kernel(float* __restrict__ P, int rows)
{
    const int row  = blockIdx.x * 8 + (threadIdx.x >> 5);
    const int lane = threadIdx.x & 31;
    if (row >= rows) return;
    float4* p = reinterpret_cast<float4*>(P + (size_t)row * Oc);
    float4 v0 = p[lane];
    float4 v1 = p[lane + 32];

    float m = fmaxf(fmaxf(fmaxf(v0.x, v0.y), fmaxf(v0.z, v0.w)),
                    fmaxf(fmaxf(v1.x, v1.y), fmaxf(v1.z, v1.w)));
#pragma unroll
    for (int o = 16; o > 0; o >>= 1)
        m = fmaxf(m, __shfl_xor_sync(0xffffffffu, m, o));

    v0.x = expf(v0.x - m); v0.y = expf(v0.y - m);
    v0.z = expf(v0.z - m); v0.w = expf(v0.w - m);
    v1.x = expf(v1.x - m); v1.y = expf(v1.y - m);
    v1.z = expf(v1.z - m); v1.w = expf(v1.w - m);

    float s = v0.x + v0.y + v0.z + v0.w + v1.x + v1.y + v1.z + v1.w;
#pragma unroll
    for (int o = 16; o > 0; o >>= 1)
        s += __shfl_xor_sync(0xffffffffu, s, o);

    const float inv = 1.0f / s;
    v0.x *= inv; v0.y *= inv; v0.z *= inv; v0.w *= inv;
    v1.x *= inv; v1.y *= inv; v1.z *= inv; v1.w *= inv;
    p[lane]      = v0;
    p[lane + 32] = v1;
}

// ---------------------------------------------------------------------------
// Launch: xw GEMM -> sequential scan -> logits GEMM -> softmax
// ---------------------------------------------------------------------------
extern "C" void kernel_launch(void* const* d_in, const int* in_sizes, int n_in,
                              void* d_out, int out_size)
{
    (void)in_sizes; (void)n_in;
    const float* x     = (const float*)d_in[0];
    const float* h0    = (const float*)d_in[1];
    const float* W_ih  = (const float*)d_in[2];
    const float* W_hh  = (const float*)d_in[3];
    const float* b_ih  = (const float*)d_in[4];
    const float* b_hh  = (const float*)d_in[5];
    const float* W_lin = (const float*)d_in[6];
    const float* b_lin = (const float*)d_in[7];
    float* outp = (float*)d_out;

    float* xw = nullptr;
    cudaGetSymbolAddress((void**)&xw, g_xw);

    // Outputs are (out, z) concatenated when out_size covers both; otherwise
    // z lives in scratch and only softmax(out) is returned.
    float* zbuf = nullptr;
    if ((long long)out_size >= (long long)BT * (Oc + Hc))
        zbuf = outp + (size_t)BT * Oc;
    else
        cudaGetSymbolAddress((void**)&zbuf, g_z);

    // 1) xw = x @ W_ih^T + (b_ih + b_hh)   [BT, H]
    gemm_tn_kernel<<<dim3(BT / 128, Hc / 128), 256>>>(
        x, W_ih, b_ih, b_hh, xw, BT, Hc, Dc);

    // 2) sequential scan -> z [B, T, H]
    rnn_scan_kernel<<<128, 512>>>(xw, h0, W_hh, zbuf);

    // 3) logits = z @ W_lin^T + b_lin  [BT, O]
    gemm_tn_kernel<<<dim3(BT / 128, Oc / 128), 256>>>(
        zbuf, W_lin, b_lin, nullptr, outp, BT, Oc, Hc);

    // 4) softmax rows in place
    softmax256_kernel<<<BT / 8, 256>>>(outp, BT);
}